// round 16
// baseline (speedup 1.0000x reference)
#include <cuda_runtime.h>
#include <cuda_bf16.h>
#include <cstdint>

// Problem constants
#define BB 2
#define SS 2048
#define DD 1024
#define HH 16
#define DKK 64
#define MM (BB*SS)      // 4096
#define BHH (BB*HH)     // 32
#define KW  256         // k-quads per 1024-wide row (int8 packing: 4 k per word)
#define DKP 32          // dk-pairs per head (64/2), bf16 attention operands

// Scratch (device globals)
__device__ float g_V[BHH*SS*DKK];                     // [bh][t][dk] fp32
__device__ float g_CtxF[MM*DD];                       // attention output fp32
// int8 GEMM operands: hi/lo s8 planes packed 4-per-word [row][k4], + scales
__device__ uint32_t g_X8h[3*MM*KW],  g_X8l[3*MM*KW];
__device__ float    g_Xs[3*MM];
__device__ uint32_t g_W8h[3*DD*KW],  g_W8l[3*DD*KW];
__device__ float    g_Ws[3*DD];
__device__ uint32_t g_Wo8h[DD*KW],   g_Wo8l[DD*KW];
__device__ float    g_Wos[DD];
__device__ uint32_t g_C8h[MM*KW],    g_C8l[MM*KW];
__device__ float    g_Cs[MM];
// bf16-pair attention operands (validated R12/R15 layout)
__device__ uint32_t g_Qph[BHH*SS*DKP], g_Qpl[BHH*SS*DKP]; // Q pairs (pre-scaled 1/8)
__device__ uint32_t g_Kph[BHH*SS*DKP], g_Kpl[BHH*SS*DKP]; // K pairs
__device__ uint32_t g_Vth[BHH*DKK*(SS/2)], g_Vtl[BHH*DKK*(SS/2)]; // V^T pairs

// ---------------------------------------------------------------------------
// helpers
// ---------------------------------------------------------------------------
__device__ __forceinline__ void mma_bf16(float c[4], const uint32_t a[4], const uint32_t b[2]) {
    asm volatile(
        "mma.sync.aligned.m16n8k16.row.col.f32.bf16.bf16.f32 "
        "{%0,%1,%2,%3}, {%4,%5,%6,%7}, {%8,%9}, {%0,%1,%2,%3};\n"
        : "+f"(c[0]), "+f"(c[1]), "+f"(c[2]), "+f"(c[3])
        : "r"(a[0]), "r"(a[1]), "r"(a[2]), "r"(a[3]), "r"(b[0]), "r"(b[1]));
}
__device__ __forceinline__ void mma_s8(int c[4], const uint32_t a[4], const uint32_t b[2]) {
    asm volatile(
        "mma.sync.aligned.m16n8k32.row.col.s32.s8.s8.s32 "
        "{%0,%1,%2,%3}, {%4,%5,%6,%7}, {%8,%9}, {%0,%1,%2,%3};\n"
        : "+r"(c[0]), "+r"(c[1]), "+r"(c[2]), "+r"(c[3])
        : "r"(a[0]), "r"(a[1]), "r"(a[2]), "r"(a[3]), "r"(b[0]), "r"(b[1]));
}
__device__ __forceinline__ void split2(float x0, float x1, uint32_t& hi, uint32_t& lo) {
    __nv_bfloat16 h0 = __float2bfloat16(x0);
    __nv_bfloat16 h1 = __float2bfloat16(x1);
    __nv_bfloat16 l0 = __float2bfloat16(x0 - __bfloat162float(h0));
    __nv_bfloat16 l1 = __float2bfloat16(x1 - __bfloat162float(h1));
    hi = (uint32_t)__bfloat16_as_ushort(h0) | ((uint32_t)__bfloat16_as_ushort(h1) << 16);
    lo = (uint32_t)__bfloat16_as_ushort(l0) | ((uint32_t)__bfloat16_as_ushort(l1) << 16);
}
__device__ __forceinline__ uint32_t pack4(int b0, int b1, int b2, int b3) {
    return (uint32_t)(b0 & 255) | ((uint32_t)(b1 & 255) << 8) |
           ((uint32_t)(b2 & 255) << 16) | ((uint32_t)(b3 & 255) << 24);
}
// 16-bit fixed-point quantize + balanced byte split (|A16|<=32384 -> hi in [-127,127])
__device__ __forceinline__ void q16(float v, float q, int& hi, int& lo) {
    int A = __float2int_rn(v * q);
    hi = (A + 128) >> 8;
    lo = A - (hi << 8);
}
#define CP_ASYNC16(dst32, src) \
    asm volatile("cp.async.cg.shared.global [%0], [%1], 16;\n" :: "r"(dst32), "l"(src) : "memory")
#define CP_COMMIT() asm volatile("cp.async.commit_group;\n" ::: "memory")
#define CP_WAIT0()  asm volatile("cp.async.wait_group 0;\n" ::: "memory")
#define CP_WAIT1()  asm volatile("cp.async.wait_group 1;\n" ::: "memory")

// block-wide max of |v| over 256 threads (red = 8-float shared scratch)
__device__ __forceinline__ float blockmax256(float v, float* red, int tid) {
    #pragma unroll
    for (int off = 16; off; off >>= 1)
        v = fmaxf(v, __shfl_xor_sync(0xffffffffu, v, off));
    if ((tid & 31) == 0) red[tid >> 5] = v;
    __syncthreads();
    float m = red[0];
    #pragma unroll
    for (int i = 1; i < 8; i++) m = fmaxf(m, red[i]);
    return m;
}

// ---------------------------------------------------------------------------
// quantize converts
// ---------------------------------------------------------------------------
// X rows (q/k/v): grid (MM, 3), block 256
__global__ void convert_x_i8(const float* __restrict__ q_, const float* __restrict__ k_,
                             const float* __restrict__ v_) {
    __shared__ float red[8];
    const int m = blockIdx.x, which = blockIdx.y;
    const float* X = (which == 0) ? q_ : (which == 1) ? k_ : v_;
    const int tid = threadIdx.x;
    float4 f = *reinterpret_cast<const float4*>(X + (size_t)m * DD + tid * 4);
    float mx = fmaxf(fmaxf(fabsf(f.x), fabsf(f.y)), fmaxf(fabsf(f.z), fabsf(f.w)));
    mx = blockmax256(mx, red, tid);
    float qs = (mx > 1e-20f) ? 32384.f / mx : 0.f;
    int h0,l0,h1,l1,h2,l2,h3,l3;
    q16(f.x, qs, h0, l0); q16(f.y, qs, h1, l1);
    q16(f.z, qs, h2, l2); q16(f.w, qs, h3, l3);
    size_t o = ((size_t)which * MM + m) * KW + tid;
    g_X8h[o] = pack4(h0, h1, h2, h3);
    g_X8l[o] = pack4(l0, l1, l2, l3);
    if (tid == 0) g_Xs[which * MM + m] = (mx > 1e-20f) ? mx / 32384.f : 0.f;
}

// W columns (n = h*64+dk, reduce over d): grid (DD, 3), block 256
__global__ void convert_w_i8(const float* __restrict__ Wq, const float* __restrict__ Wk,
                             const float* __restrict__ Wv) {
    __shared__ float red[8];
    const int n = blockIdx.x, which = blockIdx.y;
    const float* W = (which == 0) ? Wq : (which == 1) ? Wk : Wv;
    const int tid = threadIdx.x;
    const int h = n >> 6, dk = n & 63;
    const float* base = W + (size_t)h * DD * DKK + dk;
    float vals[4];
    #pragma unroll
    for (int e = 0; e < 4; e++) vals[e] = base[(size_t)(tid * 4 + e) * DKK];
    float mx = fmaxf(fmaxf(fabsf(vals[0]), fabsf(vals[1])), fmaxf(fabsf(vals[2]), fabsf(vals[3])));
    mx = blockmax256(mx, red, tid);
    float qs = (mx > 1e-20f) ? 32384.f / mx : 0.f;
    int hh[4], ll[4];
    #pragma unroll
    for (int e = 0; e < 4; e++) q16(vals[e], qs, hh[e], ll[e]);
    size_t o = ((size_t)which * DD + n) * KW + tid;
    g_W8h[o] = pack4(hh[0], hh[1], hh[2], hh[3]);
    g_W8l[o] = pack4(ll[0], ll[1], ll[2], ll[3]);
    if (tid == 0) g_Ws[which * DD + n] = (mx > 1e-20f) ? mx / 32384.f : 0.f;
}

// Wo rows (contiguous): grid DD, block 256
__global__ void convert_wo_i8(const float* __restrict__ Wo) {
    __shared__ float red[8];
    const int n = blockIdx.x;
    const int tid = threadIdx.x;
    float4 f = *reinterpret_cast<const float4*>(Wo + (size_t)n * DD + tid * 4);
    float mx = fmaxf(fmaxf(fabsf(f.x), fabsf(f.y)), fmaxf(fabsf(f.z), fabsf(f.w)));
    mx = blockmax256(mx, red, tid);
    float qs = (mx > 1e-20f) ? 32384.f / mx : 0.f;
    int h0,l0,h1,l1,h2,l2,h3,l3;
    q16(f.x, qs, h0, l0); q16(f.y, qs, h1, l1);
    q16(f.z, qs, h2, l2); q16(f.w, qs, h3, l3);
    size_t o = (size_t)n * KW + tid;
    g_Wo8h[o] = pack4(h0, h1, h2, h3);
    g_Wo8l[o] = pack4(l0, l1, l2, l3);
    if (tid == 0) g_Wos[n] = (mx > 1e-20f) ? mx / 32384.f : 0.f;
}

// Ctx rows: grid MM, block 256
__global__ void convert_ctx_i8() {
    __shared__ float red[8];
    const int m = blockIdx.x;
    const int tid = threadIdx.x;
    float4 f = *reinterpret_cast<const float4*>(g_CtxF + (size_t)m * DD + tid * 4);
    float mx = fmaxf(fmaxf(fabsf(f.x), fabsf(f.y)), fmaxf(fabsf(f.z), fabsf(f.w)));
    mx = blockmax256(mx, red, tid);
    float qs = (mx > 1e-20f) ? 32384.f / mx : 0.f;
    int h0,l0,h1,l1,h2,l2,h3,l3;
    q16(f.x, qs, h0, l0); q16(f.y, qs, h1, l1);
    q16(f.z, qs, h2, l2); q16(f.w, qs, h3, l3);
    size_t o = (size_t)m * KW + tid;
    g_C8h[o] = pack4(h0, h1, h2, h3);
    g_C8l[o] = pack4(l0, l1, l2, l3);
    if (tid == 0) g_Cs[m] = (mx > 1e-20f) ? mx / 32384.f : 0.f;
}

// transpose+split V: [bh][t][dk] fp32 -> [bh][dk][tp] bf16 pairs. grid (SS/32, BHH), block 256
__global__ void convert_vt() {
    __shared__ float sm[32][65];
    const int bh = blockIdx.y;
    const int t0 = blockIdx.x * 32;
    const int tid = threadIdx.x;
    const float* Vg = g_V + (size_t)bh * SS * DKK;
    #pragma unroll
    for (int r = 0; r < 8; r++) {
        int idx = tid + r * 256;
        int t = idx >> 6, dk = idx & 63;
        sm[t][dk] = Vg[(size_t)(t0 + t) * DKK + dk];
    }
    __syncthreads();
    const int dk = tid >> 2;
    const int pg = tid & 3;
    uint32_t* Vth = g_Vth + (size_t)bh * DKK * (SS/2) + (size_t)dk * (SS/2) + t0/2;
    uint32_t* Vtl = g_Vtl + (size_t)bh * DKK * (SS/2) + (size_t)dk * (SS/2) + t0/2;
    #pragma unroll
    for (int e = 0; e < 4; e++) {
        int p = pg * 4 + e;
        uint32_t hi, lo;
        split2(sm[2*p][dk], sm[2*p+1][dk], hi, lo);
        Vth[p] = hi;
        Vtl[p] = lo;
    }
}

// ---------------------------------------------------------------------------
// int8 GEMM core (s8x3: 65536*HH + 256*(HL+LH)). BK=64 (16 words), 16 stages,
// cp.async double-buffered. 256 threads, 8 warps (2x4), warp tile 64x32.
// smem: 2 buffers x 4 planes x [128 rows][20 words]  (same footprint as before)
// ---------------------------------------------------------------------------
#define PLANE_W 2560
#define BUF_W   (4*PLANE_W)
#define SMEM_GEMM_BYTES (2*BUF_W*4)

struct GemmPtrs { const uint32_t *Ah, *Al, *Bh, *Bl; };

__device__ __forceinline__ void gemm_issue_i8(uint32_t smem_base, const GemmPtrs& P,
                                              int m0, int n0, int s, int b, int tid) {
    const int k0 = s * 16;     // word offset within 256-word row
    #pragma unroll
    for (int r = 0; r < 8; r++) {
        int c = tid + r * 256;
        int plane = c >> 9;
        int cc = c & 511;
        int row = cc >> 2, seg = cc & 3;
        const uint32_t* srcb;
        int grow;
        if (plane == 0)      { srcb = P.Ah; grow = m0 + row; }
        else if (plane == 1) { srcb = P.Al; grow = m0 + row; }
        else if (plane == 2) { srcb = P.Bh; grow = n0 + row; }
        else                 { srcb = P.Bl; grow = n0 + row; }
        const uint32_t* src = srcb + (size_t)grow * KW + k0 + seg * 4;
        uint32_t dst = smem_base + ((b * BUF_W + plane * PLANE_W + row * 20 + seg * 4) << 2);
        CP_ASYNC16(dst, src);
    }
    CP_COMMIT();
}

__device__ __forceinline__ void gemm_compute_i8(const uint32_t* smw, int b,
                                                int wm, int wn, int g, int tg,
                                                int accHH[4][4][4], int accX[4][4][4]) {
    const uint32_t* Ah_s = smw + b * BUF_W;
    const uint32_t* Al_s = Ah_s + PLANE_W;
    const uint32_t* Bh_s = Ah_s + 2 * PLANE_W;
    const uint32_t* Bl_s = Ah_s + 3 * PLANE_W;
    #pragma unroll
    for (int kf = 0; kf < 2; kf++) {          // 2 x k32 per 64-k stage
        const int kb = kf * 8;
        uint32_t bh[4][2], bl[4][2];
        #pragma unroll
        for (int nf = 0; nf < 4; nf++) {
            int nb = wn * 32 + nf * 8 + g;
            bh[nf][0] = Bh_s[nb*20 + kb+tg]; bh[nf][1] = Bh_s[nb*20 + kb+tg+4];
            bl[nf][0] = Bl_s[nb*20 + kb+tg]; bl[nf][1] = Bl_s[nb*20 + kb+tg+4];
        }
        #pragma unroll
        for (int mf = 0; mf < 4; mf++) {
            int mb = wm * 64 + mf * 16 + g;
            uint32_t ah[4], al[4];
            ah[0] = Ah_s[(mb  )*20 + kb+tg  ]; al[0] = Al_s[(mb  )*20 + kb+tg  ];
            ah[1] = Ah_s[(mb+8)*20 + kb+tg  ]; al[1] = Al_s[(mb+8)*20 + kb+tg  ];
            ah[2] = Ah_s[(mb  )*20 + kb+tg+4]; al[2] = Al_s[(mb  )*20 + kb+tg+4];
            ah[3] = Ah_s[(mb+8)*20 + kb+tg+4]; al[3] = Al_s[(mb+8)*20 + kb+tg+4];
            #pragma unroll
            for (int nf = 0; nf < 4; nf++) {
                mma_s8(accHH[mf][nf], ah, bh[nf]);
                mma_s8(accX[mf][nf],  ah, bl[nf]);
                mma_s8(accX[mf][nf],  al, bh[nf]);
            }
        }
    }
}

__device__ __forceinline__ float recombine(int hh, int x, float ra, float rb) {
    return (65536.f * (float)hh + 256.f * (float)x) * ra * rb;
}

// ---------------------------------------------------------------------------
// Kernel: QKV projections (int8). grid (32, 8, 3), block 256.
// Q/K -> pre-split bf16 pairs (Q pre-scaled 1/8); V -> fp32.
// ---------------------------------------------------------------------------
__global__ __launch_bounds__(256) void gemm_proj_i8(void)
{
    extern __shared__ uint32_t smw[];
    const int which = blockIdx.z;
    GemmPtrs P;
    P.Ah = g_X8h + (size_t)which * MM * KW;
    P.Al = g_X8l + (size_t)which * MM * KW;
    P.Bh = g_W8h + (size_t)which * DD * KW;
    P.Bl = g_W8l + (size_t)which * DD * KW;

    const int m0 = blockIdx.x * 128;
    const int n0 = blockIdx.y * 128;
    const int tid = threadIdx.x;
    const int wid = tid >> 5, lane = tid & 31;
    const int wm = wid >> 2, wn = wid & 3;
    const int g = lane >> 2, tg = lane & 3;
    const uint32_t smem_base = (uint32_t)__cvta_generic_to_shared(smw);

    int accHH[4][4][4] = {};
    int accX[4][4][4] = {};

    gemm_issue_i8(smem_base, P, m0, n0, 0, 0, tid);
    for (int s = 0; s < 16; s++) {
        const int b = s & 1;
        CP_WAIT0();
        __syncthreads();
        if (s + 1 < 16) gemm_issue_i8(smem_base, P, m0, n0, s + 1, b ^ 1, tid);
        gemm_compute_i8(smw, b, wm, wn, g, tg, accHH, accX);
        __syncthreads();
    }

    const float qscale = (which == 0) ? 0.125f : 1.0f;
    #pragma unroll
    for (int mf = 0; mf < 4; mf++) {
        int r0 = m0 + wm * 64 + mf * 16 + g;
        int r1 = r0 + 8;
        float ra0 = g_Xs[which * MM + r0];
        float ra1 = g_Xs[which * MM + r1];
        #pragma unroll
        for (int nf = 0; nf < 4; nf++) {
            int c = n0 + wn * 32 + nf * 8 + 2 * tg;
            float rb0 = g_Ws[which * DD + c];
            float rb1 = g_Ws[which * DD + c + 1];
            float v00 = recombine(accHH[mf][nf][0], accX[mf][nf][0], ra0, rb0);
            float v01 = recombine(accHH[mf][nf][1], accX[mf][nf][1], ra0, rb1);
            float v10 = recombine(accHH[mf][nf][2], accX[mf][nf][2], ra1, rb0);
            float v11 = recombine(accHH[mf][nf][3], accX[mf][nf][3], ra1, rb1);
            int h = c >> 6, dk = c & 63;
            if (which == 2) {
                int b_ = r0 >> 11, sI = r0 & 2047;
                *reinterpret_cast<float2*>(&g_V[(((size_t)(b_ * HH + h)) * SS + sI) * DKK + dk])
                    = make_float2(v00, v01);
                b_ = r1 >> 11; sI = r1 & 2047;
                *reinterpret_cast<float2*>(&g_V[(((size_t)(b_ * HH + h)) * SS + sI) * DKK + dk])
                    = make_float2(v10, v11);
            } else {
                uint32_t* Oh = (which == 0) ? g_Qph : g_Kph;
                uint32_t* Ol = (which == 0) ? g_Qpl : g_Kpl;
                {
                    int b_ = r0 >> 11, sI = r0 & 2047;
                    size_t o = (((size_t)(b_ * HH + h)) * SS + sI) * DKP + (dk >> 1);
                    uint32_t hi, lo;
                    split2(v00 * qscale, v01 * qscale, hi, lo);
                    Oh[o] = hi; Ol[o] = lo;
                }
                {
                    int b_ = r1 >> 11, sI = r1 & 2047;
                    size_t o = (((size_t)(b_ * HH + h)) * SS + sI) * DKP + (dk >> 1);
                    uint32_t hi, lo;
                    split2(v10 * qscale, v11 * qscale, hi, lo);
                    Oh[o] = hi; Ol[o] = lo;
                }
            }
        }
    }
}

// ---------------------------------------------------------------------------
// Kernel: output projection (int8). grid (32, 8), block 256.
// ---------------------------------------------------------------------------
__global__ __launch_bounds__(256) void gemm_out_i8(const float* __restrict__ bo,
                                                   float* __restrict__ out)
{
    extern __shared__ uint32_t smw[];
    GemmPtrs P;
    P.Ah = g_C8h; P.Al = g_C8l; P.Bh = g_Wo8h; P.Bl = g_Wo8l;

    const int m0 = blockIdx.x * 128;
    const int n0 = blockIdx.y * 128;
    const int tid = threadIdx.x;
    const int wid = tid >> 5, lane = tid & 31;
    const int wm = wid >> 2, wn = wid & 3;
    const int g = lane >> 2, tg = lane & 3;
    const uint32_t smem_base = (uint32_t)__cvta_generic_to_shared(smw);

    int accHH[4][4][4] = {};
    int accX[4][4][4] = {};

    gemm_issue_i8(smem_base, P, m0, n0, 0, 0, tid);
    for (int s = 0; s < 16; s++) {
        const int b = s & 1;
        CP_WAIT0();
        __syncthreads();
        if (s + 1 < 16) gemm_issue_i8(smem_base, P, m0, n0, s + 1, b ^ 1, tid);
        gemm_compute_i8(smw, b, wm, wn, g, tg, accHH, accX);
        __syncthreads();
    }

    #pragma unroll
    for (int mf = 0; mf < 4; mf++) {
        int r0 = m0 + wm * 64 + mf * 16 + g;
        int r1 = r0 + 8;
        float ra0 = g_Cs[r0];
        float ra1 = g_Cs[r1];
        #pragma unroll
        for (int nf = 0; nf < 4; nf++) {
            int c = n0 + wn * 32 + nf * 8 + 2 * tg;
            float rb0 = g_Wos[c];
            float rb1 = g_Wos[c + 1];
            float2 bb = *reinterpret_cast<const float2*>(&bo[c]);
            float v00 = recombine(accHH[mf][nf][0], accX[mf][nf][0], ra0, rb0) + bb.x;
            float v01 = recombine(accHH[mf][nf][1], accX[mf][nf][1], ra0, rb1) + bb.y;
            float v10 = recombine(accHH[mf][nf][2], accX[mf][nf][2], ra1, rb0) + bb.x;
            float v11 = recombine(accHH[mf][nf][3], accX[mf][nf][3], ra1, rb1) + bb.y;
            *reinterpret_cast<float2*>(&out[(size_t)r0 * DD + c]) = make_float2(v00, v01);
            *reinterpret_cast<float2*>(&out[(size_t)r1 * DD + c]) = make_float2(v10, v11);
        }
    }
}

// ---------------------------------------------------------------------------
// Kernel: tensor-core causal flash attention (validated R15, K/V double-buffered).
// Only change: epilogue writes fp32 Ctx (for int8 outproj quantization).
// grid (32, 32). block 128 = 4 warps, 1x4 m-split.
// ---------------------------------------------------------------------------
#define PLW 36
#define APL (64*PLW)
#define SMEM_ATTN_BYTES (12*APL*4)   // 110592

__device__ __forceinline__ void attn_issue_kv(uint32_t sb, int buf, int j0, int tid,
                                              const uint32_t* Kh_g, const uint32_t* Kl_g,
                                              const uint32_t* Vh_g, const uint32_t* Vl_g) {
    const int base = (buf ? 8 : 2);
    #pragma unroll
    for (int r = 0; r < 4; r++) {
        int c = tid + r * 128;
        int row = c >> 3, seg = c & 7;
        CP_ASYNC16(sb + (((base+0)*APL + row*PLW + seg*4) << 2), Kh_g + (size_t)(j0+row)*DKP + seg*4);
        CP_ASYNC16(sb + (((base+1)*APL + row*PLW + seg*4) << 2), Kl_g + (size_t)(j0+row)*DKP + seg*4);
        CP_ASYNC16(sb + (((base+2)*APL + row*PLW + seg*4) << 2), Vh_g + (size_t)row*(SS/2) + j0/2 + seg*4);
        CP_ASYNC16(sb + (((base+3)*APL + row*PLW + seg*4) << 2), Vl_g + (size_t)row*(SS/2) + j0/2 + seg*4);
    }
    CP_COMMIT();
}

__global__ __launch_bounds__(128) void attn_tc()
{
    extern __shared__ uint32_t smw[];
    const int bh = blockIdx.y;
    const int qi = 31 - blockIdx.x;
    const int i0 = qi * 64;
    const int tid = threadIdx.x;
    const int wid = tid >> 5, lane = tid & 31;
    const int g = lane >> 2, tg = lane & 3;
    const int mb = wid * 16;
    const uint32_t sb = (uint32_t)__cvta_generic_to_shared(smw);

    const uint32_t* Qh_g = g_Qph + (size_t)bh * SS * DKP;
    const uint32_t* Ql_g = g_Qpl + (size_t)bh * SS * DKP;
    const uint32_t* Kh_g = g_Kph + (size_t)bh * SS * DKP;
    const uint32_t* Kl_g = g_Kpl + (size_t)bh * SS * DKP;
    const uint32_t* Vh_g = g_Vth + (size_t)bh * DKK * (SS/2);
    const uint32_t* Vl_g = g_Vtl + (size_t)bh * DKK * (SS/2);

    #pragma unroll
    for (int r = 0; r < 4; r++) {
        int c = tid + r * 128;
        int row = c >> 3, seg = c & 7;
        CP_ASYNC16(sb + ((0*APL + row*PLW + seg*4) << 2), Qh_g + (size_t)(i0+row)*DKP + seg*4);
        CP_ASYNC16(sb + ((1*APL + row*PLW + seg*4) << 2), Ql_g + (size_t)(i0+row)*DKP + seg*4);
    }
    attn_issue_kv(sb, 0, 0, tid, Kh_g, Kl_g, Vh_g, Vl_g);

    float mrow[2] = {-1e30f, -1e30f};
    float lsum[2] = {0.f, 0.f};
    float oacc[8][4] = {};

    for (int j = 0; j <= qi; j++) {
        const int buf = j & 1;
        const int j0 = j * 64;
        const int base = (buf ? 8 : 2);

        if (j < qi) {
            attn_issue_kv(sb, buf ^ 1, j0 + 64, tid, Kh_g, Kl_g, Vh_g, Vl_g);
            CP_WAIT1();
        } else {
            CP_WAIT0();
        }
        __syncthreads();

        // QK^T (bf16x3)
        float acc[8][4] = {};
        {
            const uint32_t* Qh_s = smw + 0*APL;
            const uint32_t* Ql_s = smw + 1*APL;
            const uint32_t* Kh_s = smw + (base+0)*APL;
            const uint32_t* Kl_s = smw + (base+1)*APL;
            #pragma unroll
            for (int kf = 0; kf < 4; kf++) {
                const int kb = kf * 8;
                uint32_t ah[4], al[4];
                ah[0] = Qh_s[(mb+g  )*PLW + kb+tg  ]; al[0] = Ql_s[(mb+g  )*PLW + kb+tg  ];
                ah[1] = Qh_s[(mb+g+8)*PLW + kb+tg  ]; al[1] = Ql_s[(mb+g+8)*PLW + kb+tg  ];
                ah[2] = Qh_s[(mb+g  )*PLW + kb+tg+4]; al[2] = Ql_s[(mb+g  )*PLW + kb+tg+4];
                ah[3] = Qh_s[(mb+g+8)*PLW + kb+tg+4]; al[3] = Ql_s[(mb+g+8)*PLW + kb+tg+4];
                #pragma unroll
                for (int nf = 0; nf < 8; nf++) {
                    int nb = nf * 8 + g;
                    uint32_t bh2[2], bl2[2];
                    bh2[0] = Kh_s[nb*PLW + kb+tg]; bh2[1] = Kh_s[nb*PLW + kb+tg+4];
                    bl2[0] = Kl_s[nb*PLW + kb+tg]; bl2[1] = Kl_s[nb*PLW + kb+tg+4];
                    mma_bf16(acc[nf], ah, bh2);
                    mma_bf16(acc[nf], ah, bl2);
                    mma_bf16(acc[nf], al, bh2);
                }
            }
        }

        // mask + online softmax
        const bool diag = (j == qi);
        #pragma unroll
        for (int half = 0; half < 2; half++) {
            const int r = i0 + mb + g + half * 8;
            float mx = -1e30f;
            #pragma unroll
            for (int nf = 0; nf < 8; nf++) {
                #pragma unroll
                for (int e = 0; e < 2; e++) {
                    float sv = acc[nf][half*2+e];
                    if (diag && (j0 + nf*8 + 2*tg + e) > r) {
                        sv = -1e30f;
                        acc[nf][half*2+e] = sv;
                    }
                    mx = fmaxf(mx, sv);
                }
            }
            mx = fmaxf(mx, __shfl_xor_sync(0xffffffffu, mx, 1));
            mx = fmaxf(mx, __shfl_xor_sync(0xffffffffu, mx, 2));
            float mnew = fmaxf(mrow[half], mx);
            float corr = __expf(mrow[half] - mnew);
            mrow[half] = mnew;
            float rs = 0.f;
            #pragma unroll
            for (int nf = 0; nf < 8; nf++) {
                #pragma unroll
                for (int e = 0; e < 2; e++) {
                    float p = __expf(acc[nf][half*2+e] - mnew);
                    acc[nf][half*2+e] = p;
                    rs += p;
                }
            }
            rs += __shfl_xor_sync(0xffffffffu, rs, 1);
            rs += __shfl_xor_sync(0xffffffffu, rs, 2);
            lsum[half] = lsum[half] * corr + rs;
            #pragma unroll
            for (int nf = 0; nf < 8; nf++)
                #pragma unroll
                for (int e = 0; e < 2; e++)
                    oacc[nf][half*2+e] *= corr;
        }

        // split P to bf16 pairs
        #pragma unroll
        for (int half = 0; half < 2; half++) {
            int rowi = mb + g + half * 8;
            #pragma unroll
            for (int nf = 0; nf < 8; nf++) {
                uint32_t hi, lo;
                split2(acc[nf][half*2], acc[nf][half*2+1], hi, lo);
                int idx = rowi * PLW + nf * 4 + tg;
                smw[6*APL + idx] = hi;
                smw[7*APL + idx] = lo;
            }
        }
        __syncwarp();

        // P @ V (bf16x3)
        {
            const uint32_t* Ph_s = smw + 6*APL;
            const uint32_t* Pl_s = smw + 7*APL;
            const uint32_t* Vh_s = smw + (base+2)*APL;
            const uint32_t* Vl_s = smw + (base+3)*APL;
            #pragma unroll
            for (int kf = 0; kf < 4; kf++) {
                const int kb = kf * 8;
                uint32_t ph[4], pl[4];
                ph[0] = Ph_s[(mb+g  )*PLW + kb+tg  ]; pl[0] = Pl_s[(mb+g  )*PLW + kb+tg  ];
                ph[1] = Ph_s[(mb+g+8)*PLW + kb+tg  ]; pl[1] = Pl_s[(mb+g+8)*PLW + kb+tg  ];
                ph[2] = Ph_s[(mb+g  )*PLW + kb+tg+4]; pl[2] = Pl_s[(mb+g  )*PLW + kb+tg+4];
                ph[3] = Ph_s[(mb+g+8)*PLW + kb+tg+4]; pl[3] = Pl_s[(mb+g+8)*PLW + kb+tg+4];
                #pragma unroll
                for (int nf = 0; nf < 8; nf++) {
                    int nb = nf * 8 + g;
                    uint32_t vbh[2], vbl[2];
                    vbh[0] = Vh_s[nb*PLW + kb+tg]; vbh[1] = Vh_s[nb*PLW + kb+tg+4];
                    vbl[0] = Vl_s[nb*PLW + kb+tg]; vbl[1] = Vl_s[nb*PLW + kb+tg+4];
                    mma_bf16(oacc[nf], ph, vbh);
                    mma_bf16(oacc[nf], ph, vbl);
                    mma_bf16(oacc[nf], pl, vbh);
                }
            }
        }
        __syncthreads();
    }

    // epilogue: normalize, write fp32 Ctx
    const int b_ = bh / HH, h = bh % HH;
    const float inv0 = 1.f / lsum[0];
    const float inv1 = 1.f / lsum[1];
    const int r0 = i0 + mb + g;
    #pragma unroll
    for (int nf = 0; nf < 8; nf++) {
        int col = h * 64 + nf * 8 + 2 * tg;
        *reinterpret_cast<float2*>(&g_CtxF[((size_t)(b_ * SS + r0)) * DD + col])
            = make_float2(oacc[nf][0] * inv0, oacc[nf][1] * inv0);
        *reinterpret_cast<float2*>(&g_CtxF[((size_t)(b_ * SS + r0 + 8)) * DD + col])
            = make_float2(oacc[nf][2] * inv1, oacc[nf][3] * inv1);
    }
}

// ---------------------------------------------------------------------------
extern "C" void kernel_launch(void* const* d_in, const int* in_sizes, int n_in,
                              void* d_out, int out_size)
{
    const float* q  = (const float*)d_in[0];
    const float* k  = (const float*)d_in[1];
    const float* v  = (const float*)d_in[2];
    const float* Wq = (const float*)d_in[3];
    const float* Wk = (const float*)d_in[4];
    const float* Wv = (const float*)d_in[5];
    const float* Wo = (const float*)d_in[6];
    const float* bo = (const float*)d_in[7];
    float* out = (float*)d_out;

    cudaFuncSetAttribute(gemm_proj_i8, cudaFuncAttributeMaxDynamicSharedMemorySize, SMEM_GEMM_BYTES);
    cudaFuncSetAttribute(gemm_out_i8,  cudaFuncAttributeMaxDynamicSharedMemorySize, SMEM_GEMM_BYTES);
    cudaFuncSetAttribute(attn_tc,      cudaFuncAttributeMaxDynamicSharedMemorySize, SMEM_ATTN_BYTES);

    convert_x_i8<<<dim3(MM, 3), 256>>>(q, k, v);
    convert_w_i8<<<dim3(DD, 3), 256>>>(Wq, Wk, Wv);
    convert_wo_i8<<<DD, 256>>>(Wo);

    gemm_proj_i8<<<dim3(MM / 128, DD / 128, 3), 256, SMEM_GEMM_BYTES>>>();

    convert_vt<<<dim3(SS / 32, BHH), 256>>>();

    attn_tc<<<dim3(32, BHH), 128, SMEM_ATTN_BYTES>>>();

    convert_ctx_i8<<<MM, 256>>>();

    gemm_out_i8<<<dim3(MM / 128, DD / 128), 256, SMEM_GEMM_BYTES>>>(bo, out);
}

// round 17
// speedup vs baseline: 2.0151x; 2.0151x over previous
#include <cuda_runtime.h>
#include <cuda_bf16.h>
#include <cstdint>

// Problem constants
#define BB 2
#define SS 2048
#define DD 1024
#define HH 16
#define DKK 64
#define MM (BB*SS)      // 4096
#define BHH (BB*HH)     // 32
#define KP  512         // k-pairs per 1024-wide row
#define DKP 32          // dk-pairs per head (64/2)

// Scratch (device globals)
__device__ float g_V[BHH*SS*DKK];                     // [bh][t][dk] fp32 (pre-transpose)
// packed bf16-pair planes
__device__ uint32_t g_Xh[3*MM*KP],  g_Xl[3*MM*KP];    // inputs q,k,v: [which][m][kp]
__device__ uint32_t g_Wth[3*DD*KP], g_Wtl[3*DD*KP];   // W transposed: [which][n][kp]
__device__ uint32_t g_Woh[DD*KP],   g_Wol[DD*KP];     // Wo: [n][kp]
__device__ uint32_t g_Ch[MM*KP],    g_Cl[MM*KP];      // attention out: [m][kp]
__device__ uint32_t g_Qph[BHH*SS*DKP], g_Qpl[BHH*SS*DKP]; // Q pairs (pre-scaled 1/8)
__device__ uint32_t g_Kph[BHH*SS*DKP], g_Kpl[BHH*SS*DKP]; // K pairs
__device__ uint32_t g_Vth[BHH*DKK*(SS/2)], g_Vtl[BHH*DKK*(SS/2)]; // V^T: [bh][dk][tp]

// ---------------------------------------------------------------------------
// helpers
// ---------------------------------------------------------------------------
__device__ __forceinline__ void mma_bf16(float c[4], const uint32_t a[4], const uint32_t b[2]) {
    asm volatile(
        "mma.sync.aligned.m16n8k16.row.col.f32.bf16.bf16.f32 "
        "{%0,%1,%2,%3}, {%4,%5,%6,%7}, {%8,%9}, {%0,%1,%2,%3};\n"
        : "+f"(c[0]), "+f"(c[1]), "+f"(c[2]), "+f"(c[3])
        : "r"(a[0]), "r"(a[1]), "r"(a[2]), "r"(a[3]), "r"(b[0]), "r"(b[1]));
}
__device__ __forceinline__ void ldsm4(uint32_t r[4], uint32_t addr) {
    asm volatile("ldmatrix.sync.aligned.m8n8.x4.shared.b16 {%0,%1,%2,%3}, [%4];"
        : "=r"(r[0]), "=r"(r[1]), "=r"(r[2]), "=r"(r[3]) : "r"(addr));
}
__device__ __forceinline__ void split2(float x0, float x1, uint32_t& hi, uint32_t& lo) {
    __nv_bfloat16 h0 = __float2bfloat16(x0);
    __nv_bfloat16 h1 = __float2bfloat16(x1);
    __nv_bfloat16 l0 = __float2bfloat16(x0 - __bfloat162float(h0));
    __nv_bfloat16 l1 = __float2bfloat16(x1 - __bfloat162float(h1));
    hi = (uint32_t)__bfloat16_as_ushort(h0) | ((uint32_t)__bfloat16_as_ushort(h1) << 16);
    lo = (uint32_t)__bfloat16_as_ushort(l0) | ((uint32_t)__bfloat16_as_ushort(l1) << 16);
}
#define CP_ASYNC16(dst32, src) \
    asm volatile("cp.async.cg.shared.global [%0], [%1], 16;\n" :: "r"(dst32), "l"(src) : "memory")
#define CP_COMMIT() asm volatile("cp.async.commit_group;\n" ::: "memory")
#define CP_WAIT0()  asm volatile("cp.async.wait_group 0;\n" ::: "memory")
#define CP_WAIT1()  asm volatile("cp.async.wait_group 1;\n" ::: "memory")

// ---------------------------------------------------------------------------
// convert kernels (one-shot fp32 -> packed bf16 hi/lo)  [validated R10-R15]
// ---------------------------------------------------------------------------
__global__ void convert_x(const float* __restrict__ q, const float* __restrict__ k,
                          const float* __restrict__ v) {
    int idx = blockIdx.x * 256 + threadIdx.x;
    int which = idx / (MM * 256);
    int rem = idx - which * (MM * 256);
    int m = rem >> 8, i = rem & 255;
    const float* X = (which == 0) ? q : (which == 1) ? k : v;
    float4 f = *reinterpret_cast<const float4*>(X + (size_t)m * DD + i * 4);
    uint32_t h0, l0, h1, l1;
    split2(f.x, f.y, h0, l0);
    split2(f.z, f.w, h1, l1);
    size_t o = (size_t)which * MM * KP + (size_t)m * KP + i * 2;
    *reinterpret_cast<uint2*>(&g_Xh[o]) = make_uint2(h0, h1);
    *reinterpret_cast<uint2*>(&g_Xl[o]) = make_uint2(l0, l1);
}

__global__ void convert_w(const float* __restrict__ Wq, const float* __restrict__ Wk,
                          const float* __restrict__ Wv) {
    int idx = blockIdx.x * 256 + threadIdx.x;
    int which = idx / (HH * KP * 16);
    int rem = idx - which * (HH * KP * 16);
    int dk4 = rem & 15;
    int kp = (rem >> 4) & 511;
    int h = rem >> 13;
    const float* W = (which == 0) ? Wq : (which == 1) ? Wk : Wv;
    const float* r0 = W + ((size_t)h * DD + 2 * kp) * DKK + dk4 * 4;
    float4 a = *reinterpret_cast<const float4*>(r0);
    float4 b = *reinterpret_cast<const float4*>(r0 + DKK);
    float ax[4] = {a.x, a.y, a.z, a.w};
    float bx[4] = {b.x, b.y, b.z, b.w};
    #pragma unroll
    for (int e = 0; e < 4; e++) {
        uint32_t hi, lo;
        split2(ax[e], bx[e], hi, lo);
        int n = h * 64 + dk4 * 4 + e;
        size_t o = (size_t)which * DD * KP + (size_t)n * KP + kp;
        g_Wth[o] = hi;
        g_Wtl[o] = lo;
    }
}

__global__ void convert_wo(const float* __restrict__ Wo) {
    int idx = blockIdx.x * 256 + threadIdx.x;
    int n = idx >> 8, i = idx & 255;
    float4 f = *reinterpret_cast<const float4*>(Wo + (size_t)n * DD + i * 4);
    uint32_t h0, l0, h1, l1;
    split2(f.x, f.y, h0, l0);
    split2(f.z, f.w, h1, l1);
    size_t o = (size_t)n * KP + i * 2;
    *reinterpret_cast<uint2*>(&g_Woh[o]) = make_uint2(h0, h1);
    *reinterpret_cast<uint2*>(&g_Wol[o]) = make_uint2(l0, l1);
}

// transpose+split V: [bh][t][dk] fp32 -> [bh][dk][tp] bf16 pairs. grid (SS/32, BHH), block 256
__global__ void convert_vt() {
    __shared__ float sm[32][65];
    const int bh = blockIdx.y;
    const int t0 = blockIdx.x * 32;
    const int tid = threadIdx.x;
    const float* Vg = g_V + (size_t)bh * SS * DKK;
    #pragma unroll
    for (int r = 0; r < 8; r++) {
        int idx = tid + r * 256;
        int t = idx >> 6, dk = idx & 63;
        sm[t][dk] = Vg[(size_t)(t0 + t) * DKK + dk];
    }
    __syncthreads();
    const int dk = tid >> 2;
    const int pg = tid & 3;
    uint32_t* Vth = g_Vth + (size_t)bh * DKK * (SS/2) + (size_t)dk * (SS/2) + t0/2;
    uint32_t* Vtl = g_Vtl + (size_t)bh * DKK * (SS/2) + (size_t)dk * (SS/2) + t0/2;
    #pragma unroll
    for (int e = 0; e < 4; e++) {
        int p = pg * 4 + e;
        uint32_t hi, lo;
        split2(sm[2*p][dk], sm[2*p+1][dk], hi, lo);
        Vth[p] = hi;
        Vtl[p] = lo;
    }
}

// ---------------------------------------------------------------------------
// GEMM core (bf16x3, cp.async double-buffered, LDSM fragment loads)
// 256 threads, 8 warps (2x4), warp tile 64x32. Stride 20 words (80B, 16B-aligned).
// ---------------------------------------------------------------------------
#define PLANE_W 2560
#define BUF_W   (4*PLANE_W)
#define SMEM_GEMM_BYTES (2*BUF_W*4)

struct GemmPtrs { const uint32_t *Ah, *Al, *Bh, *Bl; };

__device__ __forceinline__ void gemm_issue(uint32_t smem_base, const GemmPtrs& P,
                                           int m0, int n0, int s, int b, int tid) {
    const int kp0 = s * 16;
    #pragma unroll
    for (int r = 0; r < 8; r++) {
        int c = tid + r * 256;
        int plane = c >> 9;
        int cc = c & 511;
        int row = cc >> 2, seg = cc & 3;
        const uint32_t* srcb;
        int grow;
        if (plane == 0)      { srcb = P.Ah; grow = m0 + row; }
        else if (plane == 1) { srcb = P.Al; grow = m0 + row; }
        else if (plane == 2) { srcb = P.Bh; grow = n0 + row; }
        else                 { srcb = P.Bl; grow = n0 + row; }
        const uint32_t* src = srcb + (size_t)grow * KP + kp0 + seg * 4;
        uint32_t dst = smem_base + ((b * BUF_W + plane * PLANE_W + row * 20 + seg * 4) << 2);
        CP_ASYNC16(dst, src);
    }
    CP_COMMIT();
}

// ldmatrix-based fragment compute. Address mapping desk-verified:
//   x4 lanes l: matrix m=l>>3 row r=l&7; A matrices (m&1 -> +8 rows, m&2 -> +4 words)
//   B x4 loads two n-fragments: m>>1 selects frag, m&1 selects word half.
__device__ __forceinline__ void gemm_compute(uint32_t smem_base, int b,
                                             int wm, int wn, int lane,
                                             float acc[4][4][4]) {
    const uint32_t bufo = (uint32_t)(b * BUF_W);
    const int m_ = lane >> 3, r_ = lane & 7;
    const int a_radd = ((m_ & 1) << 3) + r_;
    const int a_cadd = (m_ & 2) << 1;          // 0 or 4
    const int b_nfsel = m_ >> 1;               // 0/1: which frag of the pair
    const int b_cadd = (m_ & 1) << 2;          // 0 or 4
    #pragma unroll
    for (int kf = 0; kf < 2; kf++) {
        const int kb = kf * 8;
        uint32_t bh[4][2], bl[4][2];
        #pragma unroll
        for (int p = 0; p < 2; p++) {
            const int nf0 = p * 2;
            const int brow = wn * 32 + (nf0 + b_nfsel) * 8 + r_;
            uint32_t baddr = smem_base + ((bufo + 2*PLANE_W + brow*20 + kb + b_cadd) << 2);
            uint32_t t[4];
            ldsm4(t, baddr);
            bh[nf0][0] = t[0]; bh[nf0][1] = t[1]; bh[nf0+1][0] = t[2]; bh[nf0+1][1] = t[3];
            ldsm4(t, baddr + (PLANE_W << 2));
            bl[nf0][0] = t[0]; bl[nf0][1] = t[1]; bl[nf0+1][0] = t[2]; bl[nf0+1][1] = t[3];
        }
        #pragma unroll
        for (int mf = 0; mf < 4; mf++) {
            const int arow = wm * 64 + mf * 16 + a_radd;
            uint32_t aaddr = smem_base + ((bufo + arow*20 + kb + a_cadd) << 2);
            uint32_t ah[4], al[4];
            ldsm4(ah, aaddr);
            ldsm4(al, aaddr + (PLANE_W << 2));
            #pragma unroll
            for (int nf = 0; nf < 4; nf++) {
                mma_bf16(acc[mf][nf], ah, bh[nf]);
                mma_bf16(acc[mf][nf], ah, bl[nf]);
                mma_bf16(acc[mf][nf], al, bh[nf]);
            }
        }
    }
}

// ---------------------------------------------------------------------------
// Kernel: QKV projections. grid (32, 8, 3), block 256.
// ---------------------------------------------------------------------------
__global__ __launch_bounds__(256, 2) void gemm_proj_tc(void)
{
    extern __shared__ uint32_t smw[];
    const int which = blockIdx.z;
    GemmPtrs P;
    P.Ah = g_Xh + (size_t)which * MM * KP;
    P.Al = g_Xl + (size_t)which * MM * KP;
    P.Bh = g_Wth + (size_t)which * DD * KP;
    P.Bl = g_Wtl + (size_t)which * DD * KP;

    const int m0 = blockIdx.x * 128;
    const int n0 = blockIdx.y * 128;
    const int tid = threadIdx.x;
    const int wid = tid >> 5, lane = tid & 31;
    const int wm = wid >> 2, wn = wid & 3;
    const int g = lane >> 2, tg = lane & 3;
    const uint32_t smem_base = (uint32_t)__cvta_generic_to_shared(smw);

    float acc[4][4][4] = {};

    gemm_issue(smem_base, P, m0, n0, 0, 0, tid);
    for (int s = 0; s < 32; s++) {
        const int b = s & 1;
        CP_WAIT0();
        __syncthreads();
        if (s + 1 < 32) gemm_issue(smem_base, P, m0, n0, s + 1, b ^ 1, tid);
        gemm_compute(smem_base, b, wm, wn, lane, acc);
        __syncthreads();
    }

    const float scale = (which == 0) ? 0.125f : 1.0f;
    #pragma unroll
    for (int mf = 0; mf < 4; mf++) {
        int r0 = m0 + wm * 64 + mf * 16 + g;
        #pragma unroll
        for (int nf = 0; nf < 4; nf++) {
            int c = n0 + wn * 32 + nf * 8 + 2 * tg;
            int h = c >> 6, dk = c & 63;
            if (which == 2) {
                int b_ = r0 >> 11, sI = r0 & 2047;
                float2 o = make_float2(acc[mf][nf][0], acc[mf][nf][1]);
                *reinterpret_cast<float2*>(&g_V[(((size_t)(b_ * HH + h)) * SS + sI) * DKK + dk]) = o;
                int r1 = r0 + 8;
                b_ = r1 >> 11; sI = r1 & 2047;
                o = make_float2(acc[mf][nf][2], acc[mf][nf][3]);
                *reinterpret_cast<float2*>(&g_V[(((size_t)(b_ * HH + h)) * SS + sI) * DKK + dk]) = o;
            } else {
                uint32_t* Oh = (which == 0) ? g_Qph : g_Kph;
                uint32_t* Ol = (which == 0) ? g_Qpl : g_Kpl;
                {
                    int b_ = r0 >> 11, sI = r0 & 2047;
                    size_t o = (((size_t)(b_ * HH + h)) * SS + sI) * DKP + (dk >> 1);
                    uint32_t hi, lo;
                    split2(acc[mf][nf][0] * scale, acc[mf][nf][1] * scale, hi, lo);
                    Oh[o] = hi; Ol[o] = lo;
                }
                {
                    int r1 = r0 + 8;
                    int b_ = r1 >> 11, sI = r1 & 2047;
                    size_t o = (((size_t)(b_ * HH + h)) * SS + sI) * DKP + (dk >> 1);
                    uint32_t hi, lo;
                    split2(acc[mf][nf][2] * scale, acc[mf][nf][3] * scale, hi, lo);
                    Oh[o] = hi; Ol[o] = lo;
                }
            }
        }
    }
}

// ---------------------------------------------------------------------------
// Kernel: output projection. grid (32, 8), block 256.
// ---------------------------------------------------------------------------
__global__ __launch_bounds__(256, 2) void gemm_out_tc(const float* __restrict__ bo,
                                                      float* __restrict__ out)
{
    extern __shared__ uint32_t smw[];
    GemmPtrs P;
    P.Ah = g_Ch; P.Al = g_Cl; P.Bh = g_Woh; P.Bl = g_Wol;

    const int m0 = blockIdx.x * 128;
    const int n0 = blockIdx.y * 128;
    const int tid = threadIdx.x;
    const int wid = tid >> 5, lane = tid & 31;
    const int wm = wid >> 2, wn = wid & 3;
    const int g = lane >> 2, tg = lane & 3;
    const uint32_t smem_base = (uint32_t)__cvta_generic_to_shared(smw);

    float acc[4][4][4] = {};

    gemm_issue(smem_base, P, m0, n0, 0, 0, tid);
    for (int s = 0; s < 32; s++) {
        const int b = s & 1;
        CP_WAIT0();
        __syncthreads();
        if (s + 1 < 32) gemm_issue(smem_base, P, m0, n0, s + 1, b ^ 1, tid);
        gemm_compute(smem_base, b, wm, wn, lane, acc);
        __syncthreads();
    }

    #pragma unroll
    for (int mf = 0; mf < 4; mf++) {
        int r0 = m0 + wm * 64 + mf * 16 + g;
        #pragma unroll
        for (int nf = 0; nf < 4; nf++) {
            int c = n0 + wn * 32 + nf * 8 + 2 * tg;
            float2 bb = *reinterpret_cast<const float2*>(&bo[c]);
            float2 o0 = make_float2(acc[mf][nf][0] + bb.x, acc[mf][nf][1] + bb.y);
            float2 o1 = make_float2(acc[mf][nf][2] + bb.x, acc[mf][nf][3] + bb.y);
            *reinterpret_cast<float2*>(&out[(size_t)r0 * DD + c]) = o0;
            *reinterpret_cast<float2*>(&out[(size_t)(r0 + 8) * DD + c]) = o1;
        }
    }
}

// ---------------------------------------------------------------------------
// Kernel: tensor-core causal flash attention, K/V double-buffered, LDSM loads.
// grid (32, 32). block 128 = 4 warps, 1x4 m-split (validated R12/R15 layout).
// smem planes (64 rows x 36 words): 0 Qh, 1 Ql, 6 Ph, 7 Pl;
//   buf0: 2 Kh,3 Kl,4 Vh,5 Vl   buf1: 8 Kh,9 Kl,10 Vh,11 Vl
// ---------------------------------------------------------------------------
#define PLW 36
#define APL (64*PLW)
#define SMEM_ATTN_BYTES (12*APL*4)   // 110592

__device__ __forceinline__ void attn_issue_kv(uint32_t sb, int buf, int j0, int tid,
                                              const uint32_t* Kh_g, const uint32_t* Kl_g,
                                              const uint32_t* Vh_g, const uint32_t* Vl_g) {
    const int base = (buf ? 8 : 2);
    #pragma unroll
    for (int r = 0; r < 4; r++) {
        int c = tid + r * 128;
        int row = c >> 3, seg = c & 7;
        CP_ASYNC16(sb + (((base+0)*APL + row*PLW + seg*4) << 2), Kh_g + (size_t)(j0+row)*DKP + seg*4);
        CP_ASYNC16(sb + (((base+1)*APL + row*PLW + seg*4) << 2), Kl_g + (size_t)(j0+row)*DKP + seg*4);
        CP_ASYNC16(sb + (((base+2)*APL + row*PLW + seg*4) << 2), Vh_g + (size_t)row*(SS/2) + j0/2 + seg*4);
        CP_ASYNC16(sb + (((base+3)*APL + row*PLW + seg*4) << 2), Vl_g + (size_t)row*(SS/2) + j0/2 + seg*4);
    }
    CP_COMMIT();
}

__global__ __launch_bounds__(128) void attn_tc()
{
    extern __shared__ uint32_t smw[];
    const int bh = blockIdx.y;
    const int qi = 31 - blockIdx.x;
    const int i0 = qi * 64;
    const int tid = threadIdx.x;
    const int wid = tid >> 5, lane = tid & 31;
    const int g = lane >> 2, tg = lane & 3;
    const int mb = wid * 16;
    const uint32_t sb = (uint32_t)__cvta_generic_to_shared(smw);

    // ldmatrix lane mapping
    const int m_ = lane >> 3, r_ = lane & 7;
    const int a_radd = ((m_ & 1) << 3) + r_;
    const int a_cadd = (m_ & 2) << 1;
    const int b_nfsel = m_ >> 1;
    const int b_cadd = (m_ & 1) << 2;

    const uint32_t* Qh_g = g_Qph + (size_t)bh * SS * DKP;
    const uint32_t* Ql_g = g_Qpl + (size_t)bh * SS * DKP;
    const uint32_t* Kh_g = g_Kph + (size_t)bh * SS * DKP;
    const uint32_t* Kl_g = g_Kpl + (size_t)bh * SS * DKP;
    const uint32_t* Vh_g = g_Vth + (size_t)bh * DKK * (SS/2);
    const uint32_t* Vl_g = g_Vtl + (size_t)bh * DKK * (SS/2);

    #pragma unroll
    for (int r = 0; r < 4; r++) {
        int c = tid + r * 128;
        int row = c >> 3, seg = c & 7;
        CP_ASYNC16(sb + ((0*APL + row*PLW + seg*4) << 2), Qh_g + (size_t)(i0+row)*DKP + seg*4);
        CP_ASYNC16(sb + ((1*APL + row*PLW + seg*4) << 2), Ql_g + (size_t)(i0+row)*DKP + seg*4);
    }
    attn_issue_kv(sb, 0, 0, tid, Kh_g, Kl_g, Vh_g, Vl_g);

    float mrow[2] = {-1e30f, -1e30f};
    float lsum[2] = {0.f, 0.f};
    float oacc[8][4] = {};

    for (int j = 0; j <= qi; j++) {
        const int buf = j & 1;
        const int j0 = j * 64;
        const int base = (buf ? 8 : 2);

        if (j < qi) {
            attn_issue_kv(sb, buf ^ 1, j0 + 64, tid, Kh_g, Kl_g, Vh_g, Vl_g);
            CP_WAIT1();
        } else {
            CP_WAIT0();
        }
        __syncthreads();

        // ---- QK^T (bf16x3) with ldmatrix ----
        float acc[8][4] = {};
        #pragma unroll
        for (int kf = 0; kf < 4; kf++) {
            const int kb = kf * 8;
            uint32_t ah[4], al[4];
            uint32_t aaddr = sb + (((uint32_t)(0*APL) + (mb + a_radd)*PLW + kb + a_cadd) << 2);
            ldsm4(ah, aaddr);
            ldsm4(al, aaddr + ((uint32_t)APL << 2));
            #pragma unroll
            for (int p = 0; p < 4; p++) {
                const int nf0 = p * 2;
                const int brow = (nf0 + b_nfsel) * 8 + r_;
                uint32_t baddr = sb + (((uint32_t)((base+0)*APL) + brow*PLW + kb + b_cadd) << 2);
                uint32_t th[4], tl[4];
                ldsm4(th, baddr);
                ldsm4(tl, baddr + ((uint32_t)APL << 2));
                uint32_t b0h[2] = {th[0], th[1]}, b1h[2] = {th[2], th[3]};
                uint32_t b0l[2] = {tl[0], tl[1]}, b1l[2] = {tl[2], tl[3]};
                mma_bf16(acc[nf0],   ah, b0h);
                mma_bf16(acc[nf0],   ah, b0l);
                mma_bf16(acc[nf0],   al, b0h);
                mma_bf16(acc[nf0+1], ah, b1h);
                mma_bf16(acc[nf0+1], ah, b1l);
                mma_bf16(acc[nf0+1], al, b1h);
            }
        }

        // ---- mask + online softmax (full row inside this warp) ----
        const bool diag = (j == qi);
        #pragma unroll
        for (int half = 0; half < 2; half++) {
            const int r = i0 + mb + g + half * 8;
            float mx = -1e30f;
            #pragma unroll
            for (int nf = 0; nf < 8; nf++) {
                #pragma unroll
                for (int e = 0; e < 2; e++) {
                    float sv = acc[nf][half*2+e];
                    if (diag && (j0 + nf*8 + 2*tg + e) > r) {
                        sv = -1e30f;
                        acc[nf][half*2+e] = sv;
                    }
                    mx = fmaxf(mx, sv);
                }
            }
            mx = fmaxf(mx, __shfl_xor_sync(0xffffffffu, mx, 1));
            mx = fmaxf(mx, __shfl_xor_sync(0xffffffffu, mx, 2));
            float mnew = fmaxf(mrow[half], mx);
            float corr = __expf(mrow[half] - mnew);
            mrow[half] = mnew;
            float rs = 0.f;
            #pragma unroll
            for (int nf = 0; nf < 8; nf++) {
                #pragma unroll
                for (int e = 0; e < 2; e++) {
                    float p = __expf(acc[nf][half*2+e] - mnew);
                    acc[nf][half*2+e] = p;
                    rs += p;
                }
            }
            rs += __shfl_xor_sync(0xffffffffu, rs, 1);
            rs += __shfl_xor_sync(0xffffffffu, rs, 2);
            lsum[half] = lsum[half] * corr + rs;
            #pragma unroll
            for (int nf = 0; nf < 8; nf++)
                #pragma unroll
                for (int e = 0; e < 2; e++)
                    oacc[nf][half*2+e] *= corr;
        }

        // ---- split P to bf16 pairs in smem (planes 6/7) ----
        #pragma unroll
        for (int half = 0; half < 2; half++) {
            int rowi = mb + g + half * 8;
            #pragma unroll
            for (int nf = 0; nf < 8; nf++) {
                uint32_t hi, lo;
                split2(acc[nf][half*2], acc[nf][half*2+1], hi, lo);
                int idx = rowi * PLW + nf * 4 + tg;
                smw[6*APL + idx] = hi;
                smw[7*APL + idx] = lo;
            }
        }
        __syncwarp();   // P rows are private to this warp

        // ---- P @ V (bf16x3) with ldmatrix ----
        #pragma unroll
        for (int kf = 0; kf < 4; kf++) {
            const int kb = kf * 8;
            uint32_t ph[4], pl[4];
            uint32_t paddr = sb + (((uint32_t)(6*APL) + (mb + a_radd)*PLW + kb + a_cadd) << 2);
            ldsm4(ph, paddr);
            ldsm4(pl, paddr + ((uint32_t)APL << 2));
            #pragma unroll
            for (int p = 0; p < 4; p++) {
                const int nf0 = p * 2;
                const int brow = (nf0 + b_nfsel) * 8 + r_;
                uint32_t vaddr = sb + (((uint32_t)((base+2)*APL) + brow*PLW + kb + b_cadd) << 2);
                uint32_t th[4], tl[4];
                ldsm4(th, vaddr);
                ldsm4(tl, vaddr + ((uint32_t)APL << 2));
                uint32_t b0h[2] = {th[0], th[1]}, b1h[2] = {th[2], th[3]};
                uint32_t b0l[2] = {tl[0], tl[1]}, b1l[2] = {tl[2], tl[3]};
                mma_bf16(oacc[nf0],   ph, b0h);
                mma_bf16(oacc[nf0],   ph, b0l);
                mma_bf16(oacc[nf0],   pl, b0h);
                mma_bf16(oacc[nf0+1], ph, b1h);
                mma_bf16(oacc[nf0+1], ph, b1l);
                mma_bf16(oacc[nf0+1], pl, b1h);
            }
        }
        __syncthreads();   // all warps done with buf before it is re-issued (j+2)
    }

    // ---- epilogue: normalize, split, write Ctx pairs ----
    const int b_ = bh / HH, h = bh % HH;
    const float inv0 = 1.f / lsum[0];
    const float inv1 = 1.f / lsum[1];
    const int r0 = i0 + mb + g;
    #pragma unroll
    for (int nf = 0; nf < 8; nf++) {
        int pidx = h * 32 + nf * 4 + tg;
        {
            size_t o = ((size_t)(b_ * SS + r0)) * KP + pidx;
            uint32_t hi, lo;
            split2(oacc[nf][0] * inv0, oacc[nf][1] * inv0, hi, lo);
            g_Ch[o] = hi; g_Cl[o] = lo;
        }
        {
            size_t o = ((size_t)(b_ * SS + r0 + 8)) * KP + pidx;
            uint32_t hi, lo;
            split2(oacc[nf][2] * inv1, oacc[nf][3] * inv1, hi, lo);
            g_Ch[o] = hi; g_Cl[o] = lo;
        }
    }
}

// ---------------------------------------------------------------------------
extern "C" void kernel_launch(void* const* d_in, const int* in_sizes, int n_in,
                              void* d_out, int out_size)
{
    const float* q  = (const float*)d_in[0];
    const float* k  = (const float*)d_in[1];
    const float* v  = (const float*)d_in[2];
    const float* Wq = (const float*)d_in[3];
    const float* Wk = (const float*)d_in[4];
    const float* Wv = (const float*)d_in[5];
    const float* Wo = (const float*)d_in[6];
    const float* bo = (const float*)d_in[7];
    float* out = (float*)d_out;

    cudaFuncSetAttribute(gemm_proj_tc, cudaFuncAttributeMaxDynamicSharedMemorySize, SMEM_GEMM_BYTES);
    cudaFuncSetAttribute(gemm_out_tc,  cudaFuncAttributeMaxDynamicSharedMemorySize, SMEM_GEMM_BYTES);
    cudaFuncSetAttribute(attn_tc,      cudaFuncAttributeMaxDynamicSharedMemorySize, SMEM_ATTN_BYTES);

    convert_x<<<3 * MM, 256>>>(q, k, v);
    convert_w<<<3 * HH * KP * 16 / 256, 256>>>(Wq, Wk, Wv);
    convert_wo<<<DD, 256>>>(Wo);

    gemm_proj_tc<<<dim3(MM / 128, DD / 128, 3), 256, SMEM_GEMM_BYTES>>>();

    convert_vt<<<dim3(SS / 32, BHH), 256>>>();

    attn_tc<<<dim3(32, BHH), 128, SMEM_ATTN_BYTES>>>();

    gemm_out_tc<<<dim3(MM / 128, DD / 128), 256, SMEM_GEMM_BYTES>>>(bo, out);
}